// round 3
// baseline (speedup 1.0000x reference)
#include <cuda_runtime.h>
#include <cstddef>
#include <cstdint>

// ---------------------------------------------------------------------------
// Problem constants
// ---------------------------------------------------------------------------
#define NC 100000
#define NM 50000
#define ND 10000

// Scratch layout (4-byte units). ALL region sizes are multiples of 4 words so
// every region base stays 16-byte aligned (float4 access safety).
//   OFF : 320,008 ints  (per-relation CSR offsets, NDST+1 each; padded)
//   CUR : 320,000 ints  (fill cursors)
//   CSR : 4,800,000 ints (edge src ids grouped by dst, per relation)
//   P   : 6,400,000 f   (projected source features, reused per relation)
//   AGG : 20,480,000 f  (per-relation aggregated means)
//   H   : 10,240,000 f  (layer-1 hidden states)
#define OFF_WORDS 320008ull
#define CUR_WORDS 320000ull
#define CSR_WORDS 4800000ull
#define P_WORDS   6400000ull
#define AGG_WORDS 20480000ull
#define H_WORDS   10240000ull
#define SCRATCH_WORDS (OFF_WORDS + CUR_WORDS + CSR_WORDS + P_WORDS + AGG_WORDS + H_WORDS)
__device__ __align__(16) float g_scratch[SCRATCH_WORDS];

// ---------------------------------------------------------------------------
// Utility kernels
// ---------------------------------------------------------------------------
__global__ void zero_int_kernel(int* __restrict__ p, int n) {
    int i = blockIdx.x * blockDim.x + threadIdx.x;
    if (i < n) p[i] = 0;
}

__global__ void count_kernel(const int* __restrict__ dst, int E, int* __restrict__ cnt1) {
    int i = blockIdx.x * blockDim.x + threadIdx.x;
    if (i < E) atomicAdd(&cnt1[dst[i] + 1], 1);
}

struct ScanArgs { int* data[6]; int n[6]; };

// One block per relation: inclusive scan of data[0..n] (data[0]==0 on entry).
__global__ void scan_kernel(ScanArgs a) {
    __shared__ int tmp[1024];
    __shared__ int carry;
    int* data = a.data[blockIdx.x];
    int n = a.n[blockIdx.x];
    int t = threadIdx.x;
    if (t == 0) carry = 0;
    __syncthreads();
    for (int base = 0; base <= n; base += 1024) {
        int i = base + t;
        int v = (i <= n) ? data[i] : 0;
        tmp[t] = v;
        __syncthreads();
        #pragma unroll
        for (int o = 1; o < 1024; o <<= 1) {
            int u = (t >= o) ? tmp[t - o] : 0;
            __syncthreads();
            tmp[t] += u;
            __syncthreads();
        }
        if (i <= n) data[i] = tmp[t] + carry;
        __syncthreads();
        if (t == 0) carry += tmp[1023];
        __syncthreads();
    }
}

__global__ void fill_kernel(const int* __restrict__ src, const int* __restrict__ dst,
                            int E, const int* __restrict__ off,
                            int* __restrict__ cur, int* __restrict__ csr) {
    int e = blockIdx.x * blockDim.x + threadIdx.x;
    if (e < E) {
        int d = dst[e];
        int p = off[d] + atomicAdd(&cur[d], 1);
        csr[p] = src[e];
    }
}

// ---------------------------------------------------------------------------
// Gather: one warp per destination node; mean of projected source rows.
// ---------------------------------------------------------------------------
__global__ __launch_bounds__(256)
void gather_kernel(const float* __restrict__ P, const int* __restrict__ off,
                   const int* __restrict__ csr, float* __restrict__ out, int n) {
    int w = (blockIdx.x * blockDim.x + threadIdx.x) >> 5;
    int lane = threadIdx.x & 31;
    if (w >= n) return;
    int s = off[w], e = off[w + 1];
    float a0 = 0.f, a1 = 0.f, b0 = 0.f, b1 = 0.f;
    int i = s;
    for (; i + 4 <= e; i += 4) {
        int s0 = csr[i], s1 = csr[i + 1], s2 = csr[i + 2], s3 = csr[i + 3];
        const float* p0 = P + (size_t)s0 * 64;
        const float* p1 = P + (size_t)s1 * 64;
        const float* p2 = P + (size_t)s2 * 64;
        const float* p3 = P + (size_t)s3 * 64;
        float x0 = p0[lane], y0 = p0[32 + lane];
        float x1 = p1[lane], y1 = p1[32 + lane];
        float x2 = p2[lane], y2 = p2[32 + lane];
        float x3 = p3[lane], y3 = p3[32 + lane];
        a0 += x0 + x1; b0 += x2 + x3;
        a1 += y0 + y1; b1 += y2 + y3;
    }
    for (; i < e; i++) {
        const float* p0 = P + (size_t)csr[i] * 64;
        a0 += p0[lane];
        a1 += p0[32 + lane];
    }
    a0 += b0; a1 += b1;
    int deg = e - s;
    float sc = 1.0f / (float)(deg > 1 ? deg : 1);
    out[(size_t)w * 64 + lane] = a0 * sc;
    out[(size_t)w * 64 + 32 + lane] = a1 * sc;
}

// ---------------------------------------------------------------------------
// GEMM: Y[M,64] = X[M,K] @ W[K,64] (+ optional W1 fused), fused epilogues.
//   mode 0: Y = X @ W0
//   mode 1: Y = relu(0.5*(X@(W0+W1) + aggA + aggB + b0 + b1))
//   mode 2: as 1, no relu
//   mode 3: Y += X @ W0 + b0
// Block = 256 rows x 64 cols, 256 threads, 8x8 micro-tile.
// Xs: row-major, odd stride 33 -> conflict-free scalar a-loads and stores.
// Ws: 4-word gap after col 32 -> the 8 float4 b-reads cover all 32 banks.
// ---------------------------------------------------------------------------
template<int K>
__global__ __launch_bounds__(256)
void gemm_kernel(const float* __restrict__ X,
                 const float* __restrict__ W0, const float* __restrict__ W1,
                 const float* __restrict__ b0, const float* __restrict__ b1,
                 const float* __restrict__ aggA, const float* __restrict__ aggB,
                 float* __restrict__ Y, int M, int mode) {
    constexpr int BM = 256, KT = 32;
    __shared__ float Xs[BM][33];   // 33.8 KB
    __shared__ float Ws[KT][72];   // 9.2 KB (gap at col 32)

    const int t = threadIdx.x;
    const int m0 = blockIdx.x * BM;

    // X loader: rows rowg + 32*it, k-chunk kq*4 (coalesced 128B per 4-row group)
    const int kq = t & 7;
    const int rowg = t >> 3;
    // W loader
    const int kw = t >> 3;       // 0..31
    const int cw = t & 7;        // col group cw*8
    const int cws = cw * 8 + ((cw >= 4) ? 4 : 0);
    // math mapping
    const int rr = (t & 3) + ((t >> 5) << 2);   // 0..31
    const int cc = (t >> 2) & 7;                // 0..7
    const int r0 = rr * 8;
    const int c0 = cc * 8;
    const int c0s = c0 + ((cc >= 4) ? 4 : 0);

    float acc[8][8];
    #pragma unroll
    for (int i = 0; i < 8; i++)
        #pragma unroll
        for (int j = 0; j < 8; j++) acc[i][j] = 0.f;

    for (int kb = 0; kb < K; kb += KT) {
        // ---- load X tile ----
        #pragma unroll
        for (int it = 0; it < 8; it++) {
            int ml = rowg + 32 * it;
            int m = m0 + ml;
            float4 v = make_float4(0.f, 0.f, 0.f, 0.f);
            if (m < M) v = *(const float4*)(X + (size_t)m * K + kb + kq * 4);
            Xs[ml][kq * 4 + 0] = v.x;
            Xs[ml][kq * 4 + 1] = v.y;
            Xs[ml][kq * 4 + 2] = v.z;
            Xs[ml][kq * 4 + 3] = v.w;
        }
        // ---- load W tile (optionally W0+W1) ----
        {
            const float* wp = W0 + (size_t)(kb + kw) * 64 + cw * 8;
            float4 wa = *(const float4*)(wp);
            float4 wb = *(const float4*)(wp + 4);
            if (W1) {
                const float* wq = W1 + (size_t)(kb + kw) * 64 + cw * 8;
                float4 va = *(const float4*)(wq);
                float4 vb = *(const float4*)(wq + 4);
                wa.x += va.x; wa.y += va.y; wa.z += va.z; wa.w += va.w;
                wb.x += vb.x; wb.y += vb.y; wb.z += vb.z; wb.w += vb.w;
            }
            *(float4*)(&Ws[kw][cws]) = wa;
            *(float4*)(&Ws[kw][cws + 4]) = wb;
        }
        __syncthreads();

        #pragma unroll 8
        for (int k = 0; k < KT; k++) {
            float a[8];
            #pragma unroll
            for (int i = 0; i < 8; i++) a[i] = Xs[r0 + i][k];
            float4 bx = *(const float4*)(&Ws[k][c0s]);
            float4 by = *(const float4*)(&Ws[k][c0s + 4]);
            float bb[8] = {bx.x, bx.y, bx.z, bx.w, by.x, by.y, by.z, by.w};
            #pragma unroll
            for (int i = 0; i < 8; i++)
                #pragma unroll
                for (int j = 0; j < 8; j++)
                    acc[i][j] = fmaf(a[i], bb[j], acc[i][j]);
        }
        __syncthreads();
    }

    // ---- epilogue ----
    #pragma unroll
    for (int i = 0; i < 8; i++) {
        int m = m0 + r0 + i;
        if (m >= M) break;
        size_t base = (size_t)m * 64;
        if (mode == 0) {
            float4 v0 = make_float4(acc[i][0], acc[i][1], acc[i][2], acc[i][3]);
            float4 v1 = make_float4(acc[i][4], acc[i][5], acc[i][6], acc[i][7]);
            *(float4*)(Y + base + c0) = v0;
            *(float4*)(Y + base + c0 + 4) = v1;
        } else if (mode == 3) {
            #pragma unroll
            for (int j = 0; j < 8; j++) {
                int c = c0 + j;
                Y[base + c] += acc[i][j] + b0[c];
            }
        } else {
            #pragma unroll
            for (int j = 0; j < 8; j++) {
                int c = c0 + j;
                float v = 0.5f * (acc[i][j] + aggA[base + c] + aggB[base + c]
                                  + b0[c] + b1[c]);
                if (mode == 1) v = fmaxf(v, 0.0f);
                Y[base + c] = v;
            }
        }
    }
}

// ---------------------------------------------------------------------------
// Row-wise L2 normalization: one warp per 64-wide row.
// ---------------------------------------------------------------------------
__global__ void l2norm_kernel(float* __restrict__ Y, int rows) {
    int gw = (blockIdx.x * blockDim.x + threadIdx.x) >> 5;
    int lane = threadIdx.x & 31;
    if (gw >= rows) return;
    size_t base = (size_t)gw * 64;
    float a = Y[base + lane];
    float b = Y[base + 32 + lane];
    float s = a * a + b * b;
    #pragma unroll
    for (int off = 16; off > 0; off >>= 1)
        s += __shfl_xor_sync(0xffffffffu, s, off);
    float inv = 1.0f / fmaxf(sqrtf(s), 1e-12f);
    Y[base + lane] = a * inv;
    Y[base + 32 + lane] = b * inv;
}

// ---------------------------------------------------------------------------
// Host orchestration
// ---------------------------------------------------------------------------
extern "C" void kernel_launch(void* const* d_in, const int* in_sizes, int n_in,
                              void* d_out, int out_size) {
    const float* xc = (const float*)d_in[0];
    const float* xm = (const float*)d_in[1];
    const float* xd = (const float*)d_in[2];
    // relation order: 0=c->m, 1=m->d, 2=c->d, 3=m->c, 4=d->m, 5=d->c
    const int srcIdx[6] = {3, 5, 7, 9, 11, 13};
    const int dstIdx[6] = {4, 6, 8, 10, 12, 14};
    const int* SRC[6]; const int* DST[6]; int EE[6];
    for (int r = 0; r < 6; r++) {
        SRC[r] = (const int*)d_in[srcIdx[r]];
        DST[r] = (const int*)d_in[dstIdx[r]];
        EE[r]  = in_sizes[srcIdx[r]];
    }
    const float* W1l  = (const float*)d_in[15];
    const float* W1r  = (const float*)d_in[16];
    const float* b1   = (const float*)d_in[17];
    const float* W2l  = (const float*)d_in[18];
    const float* W2r  = (const float*)d_in[19];
    const float* b2   = (const float*)d_in[20];
    const float* Wres = (const float*)d_in[21];
    const float* bres = (const float*)d_in[22];
    float* out = (float*)d_out;

    const int NSRC[6]    = {NC, NM, NC, NM, ND, ND};
    const int NDSTA[6]   = {NM, ND, ND, NC, NM, NC};
    const int srcType[6] = {0, 1, 0, 1, 2, 2};  // 0=c,1=m,2=d

    float* S = nullptr;
    cudaGetSymbolAddress((void**)&S, g_scratch);

    int*   OFF = (int*)S;
    int*   CUR = OFF + OFF_WORDS;
    int*   CSR = CUR + CUR_WORDS;
    float* P   = (float*)(CSR + CSR_WORDS);
    float* AGG = P + P_WORDS;
    float* H   = AGG + AGG_WORDS;

    int* offR[6]; int* curR[6]; int* csrR[6];
    size_t aOff[6];
    {
        size_t o = 0, c = 0, e = 0, a = 0;
        for (int r = 0; r < 6; r++) {
            offR[r] = OFF + o;  o += (size_t)NDSTA[r] + 1;
            curR[r] = CUR + c;  c += (size_t)NDSTA[r];
            csrR[r] = CSR + e;  e += (size_t)EE[r];
            aOff[r] = a;        a += (size_t)NDSTA[r] * 64;
        }
    }

    float* Hc = H;
    float* Hm = Hc + (size_t)NC * 64;
    float* Hd = Hm + (size_t)NM * 64;
    const float* X1[3] = {xc, xm, xd};
    const float* HX[3] = {Hc, Hm, Hd};

    float* Oc = out;
    float* Om = Oc + (size_t)NC * 64;
    float* Od = Om + (size_t)NM * 64;

    // ---- build CSR (shared by both layers) ----
    {
        int nz = (int)(OFF_WORDS + CUR_WORDS);
        zero_int_kernel<<<(nz + 255) / 256, 256>>>(OFF, nz);
    }
    for (int r = 0; r < 6; r++)
        count_kernel<<<(EE[r] + 255) / 256, 256>>>(DST[r], EE[r], offR[r]);
    {
        ScanArgs sa;
        for (int r = 0; r < 6; r++) { sa.data[r] = offR[r]; sa.n[r] = NDSTA[r]; }
        scan_kernel<<<6, 1024>>>(sa);
    }
    for (int r = 0; r < 6; r++)
        fill_kernel<<<(EE[r] + 255) / 256, 256>>>(SRC[r], DST[r], EE[r],
                                                  offR[r], curR[r], csrR[r]);

    // ---- layer 1 (F=128 -> 64) ----
    for (int r = 0; r < 6; r++) {
        int M = NSRC[r];
        gemm_kernel<128><<<(M + 255) / 256, 256>>>(
            X1[srcType[r]], W1l + (size_t)r * 8192, nullptr,
            nullptr, nullptr, nullptr, nullptr, P, M, 0);
        gather_kernel<<<(NDSTA[r] * 32 + 255) / 256, 256>>>(
            P, offR[r], csrR[r], AGG + aOff[r], NDSTA[r]);
    }
    // combines: m <- (0,4), d <- (1,2), c <- (3,5)
    gemm_kernel<128><<<(NM + 255) / 256, 256>>>(
        xm, W1r + 0 * 8192, W1r + 4 * 8192, b1 + 0 * 64, b1 + 4 * 64,
        AGG + aOff[0], AGG + aOff[4], Hm, NM, 1);
    gemm_kernel<128><<<(ND + 255) / 256, 256>>>(
        xd, W1r + 1 * 8192, W1r + 2 * 8192, b1 + 1 * 64, b1 + 2 * 64,
        AGG + aOff[1], AGG + aOff[2], Hd, ND, 1);
    gemm_kernel<128><<<(NC + 255) / 256, 256>>>(
        xc, W1r + 3 * 8192, W1r + 5 * 8192, b1 + 3 * 64, b1 + 5 * 64,
        AGG + aOff[3], AGG + aOff[5], Hc, NC, 1);

    // ---- layer 2 (F=64 -> 64) ----
    for (int r = 0; r < 6; r++) {
        int M = NSRC[r];
        gemm_kernel<64><<<(M + 255) / 256, 256>>>(
            HX[srcType[r]], W2l + (size_t)r * 4096, nullptr,
            nullptr, nullptr, nullptr, nullptr, P, M, 0);
        gather_kernel<<<(NDSTA[r] * 32 + 255) / 256, 256>>>(
            P, offR[r], csrR[r], AGG + aOff[r], NDSTA[r]);
    }
    gemm_kernel<64><<<(NM + 255) / 256, 256>>>(
        Hm, W2r + 0 * 4096, W2r + 4 * 4096, b2 + 0 * 64, b2 + 4 * 64,
        AGG + aOff[0], AGG + aOff[4], Om, NM, 2);
    gemm_kernel<64><<<(ND + 255) / 256, 256>>>(
        Hd, W2r + 1 * 4096, W2r + 2 * 4096, b2 + 1 * 64, b2 + 2 * 64,
        AGG + aOff[1], AGG + aOff[2], Od, ND, 2);
    gemm_kernel<64><<<(NC + 255) / 256, 256>>>(
        Hc, W2r + 3 * 4096, W2r + 5 * 4096, b2 + 3 * 64, b2 + 5 * 64,
        AGG + aOff[3], AGG + aOff[5], Oc, NC, 2);

    // ---- residual projections (K=128) ----
    gemm_kernel<128><<<(NC + 255) / 256, 256>>>(
        xc, Wres + 0 * 8192, nullptr, bres + 0 * 64, nullptr,
        nullptr, nullptr, Oc, NC, 3);
    gemm_kernel<128><<<(NM + 255) / 256, 256>>>(
        xm, Wres + 1 * 8192, nullptr, bres + 1 * 64, nullptr,
        nullptr, nullptr, Om, NM, 3);
    gemm_kernel<128><<<(ND + 255) / 256, 256>>>(
        xd, Wres + 2 * 8192, nullptr, bres + 2 * 64, nullptr,
        nullptr, nullptr, Od, ND, 3);

    // ---- row-wise L2 norm ----
    const int rows = NC + NM + ND;
    l2norm_kernel<<<(rows * 32 + 255) / 256, 256>>>(out, rows);
}

// round 4
// speedup vs baseline: 1.4343x; 1.4343x over previous
#include <cuda_runtime.h>
#include <cstddef>
#include <cstdint>

typedef unsigned long long ull;

// ---------------------------------------------------------------------------
// Problem constants
// ---------------------------------------------------------------------------
#define NC 100000
#define NM 50000
#define ND 10000

// Scratch layout (4-byte words, every region base 16B-aligned):
//   OFF : 320,008   (per-relation CSR offsets, NDST+1 each; padded)
//   CUR : 320,000   (fill cursors)
//   CSR : 4,800,000 (edge src ids grouped by dst, per relation)
//   P   : 20,480,000 (per-relation projected source features, 320k rows x 64)
//   AGG : 10,240,000 (merged per-dst-type aggregated means, 160k x 64)
//   H   : 10,240,000 (layer-1 hidden states)
#define OFF_WORDS 320008ull
#define CUR_WORDS 320000ull
#define CSR_WORDS 4800000ull
#define P_WORDS   20480000ull
#define AGG_WORDS 10240000ull
#define H_WORDS   10240000ull
#define SCRATCH_WORDS (OFF_WORDS + CUR_WORDS + CSR_WORDS + P_WORDS + AGG_WORDS + H_WORDS)
__device__ __align__(16) float g_scratch[SCRATCH_WORDS];

// ---------------------------------------------------------------------------
// f32x2 packed helpers (Blackwell FFMA2 path: 2x fp32 FMA throughput)
// ---------------------------------------------------------------------------
__device__ __forceinline__ ull splat2(float x) {
    ull r; asm("mov.b64 %0, {%1, %1};" : "=l"(r) : "f"(x)); return r;
}
__device__ __forceinline__ ull pack2(float lo, float hi) {
    ull r; asm("mov.b64 %0, {%1, %2};" : "=l"(r) : "f"(lo), "f"(hi)); return r;
}
__device__ __forceinline__ void unpack2(ull v, float& lo, float& hi) {
    asm("mov.b64 {%0, %1}, %2;" : "=f"(lo), "=f"(hi) : "l"(v));
}
__device__ __forceinline__ void fma2(ull& d, ull a, ull b) {
    asm("fma.rn.f32x2 %0, %1, %2, %0;" : "+l"(d) : "l"(a), "l"(b));
}
__device__ __forceinline__ ull add2(ull a, ull b) {
    ull r; asm("add.rn.f32x2 %0, %1, %2;" : "=l"(r) : "l"(a), "l"(b)); return r;
}
__device__ __forceinline__ ull mul2(ull a, ull b) {
    ull r; asm("mul.rn.f32x2 %0, %1, %2;" : "=l"(r) : "l"(a), "l"(b)); return r;
}

// ---------------------------------------------------------------------------
// CSR build kernels (all relations fused per kernel)
// ---------------------------------------------------------------------------
__global__ void zero_int_kernel(int* __restrict__ p, int n) {
    int i = blockIdx.x * blockDim.x + threadIdx.x;
    if (i < n) p[i] = 0;
}

struct Edge6 {
    const int* src[6]; const int* dst[6];
    int* cnt[6]; int* cur[6]; int* csr[6];
    int bs[7]; int E[6];
};

__global__ void count_all(Edge6 a) {
    int b = blockIdx.x, r = 0;
    while (b >= a.bs[r + 1]) r++;
    int e = (b - a.bs[r]) * 256 + threadIdx.x;
    if (e < a.E[r]) atomicAdd(&a.cnt[r][a.dst[r][e] + 1], 1);
}

__global__ void fill_all(Edge6 a) {
    int b = blockIdx.x, r = 0;
    while (b >= a.bs[r + 1]) r++;
    int e = (b - a.bs[r]) * 256 + threadIdx.x;
    if (e < a.E[r]) {
        int d = a.dst[r][e];
        int p = a.cnt[r][d] + atomicAdd(&a.cur[r][d], 1);
        a.csr[r][p] = a.src[r][e];
    }
}

struct ScanArgs { int* data[6]; int n[6]; };

// One block per relation; inclusive scan of data[0..n] via warp shuffles.
__global__ __launch_bounds__(1024) void scan6(ScanArgs a) {
    __shared__ int wsum[33];
    int* data = a.data[blockIdx.x];
    int n = a.n[blockIdx.x];
    int t = threadIdx.x, lane = t & 31, wid = t >> 5;
    int carry = 0;
    for (int base = 0; base <= n; base += 4096) {
        int i0 = base + t * 4;
        int v0 = (i0     <= n) ? data[i0]     : 0;
        int v1 = (i0 + 1 <= n) ? data[i0 + 1] : 0;
        int v2 = (i0 + 2 <= n) ? data[i0 + 2] : 0;
        int v3 = (i0 + 3 <= n) ? data[i0 + 3] : 0;
        int s01 = v0 + v1;
        int s = s01 + v2 + v3;
        int sc = s;
        #pragma unroll
        for (int o = 1; o < 32; o <<= 1) {
            int u = __shfl_up_sync(0xffffffffu, sc, o);
            if (lane >= o) sc += u;
        }
        if (lane == 31) wsum[wid] = sc;
        __syncthreads();
        if (wid == 0) {
            int w = wsum[lane];
            int wc = w;
            #pragma unroll
            for (int o = 1; o < 32; o <<= 1) {
                int u = __shfl_up_sync(0xffffffffu, wc, o);
                if (lane >= o) wc += u;
            }
            wsum[lane] = wc;
            if (lane == 31) wsum[32] = wc;
        }
        __syncthreads();
        int prefix = carry + (wid ? wsum[wid - 1] : 0) + (sc - s);
        if (i0     <= n) data[i0]     = prefix + v0;
        if (i0 + 1 <= n) data[i0 + 1] = prefix + s01;
        if (i0 + 2 <= n) data[i0 + 2] = prefix + s01 + v2;
        if (i0 + 3 <= n) data[i0 + 3] = prefix + s;
        carry += wsum[32];
        __syncthreads();
    }
}

// ---------------------------------------------------------------------------
// Merged dual-relation gather: one warp per destination node, 3 dst types.
// Each lane owns 2 consecutive columns (ld.64 + add.rn.f32x2).
// ---------------------------------------------------------------------------
__device__ __forceinline__ ull gather_rel(const float* __restrict__ P,
                                          const int* __restrict__ off,
                                          const int* __restrict__ csr,
                                          int w, int lane, float& sc) {
    int s = off[w], e = off[w + 1];
    ull a0 = 0ull, a1 = 0ull;
    int i = s;
    for (; i + 4 <= e; i += 4) {
        int s0 = csr[i], s1 = csr[i + 1], s2 = csr[i + 2], s3 = csr[i + 3];
        ull v0 = *(const ull*)(P + (size_t)s0 * 64 + lane * 2);
        ull v1 = *(const ull*)(P + (size_t)s1 * 64 + lane * 2);
        ull v2 = *(const ull*)(P + (size_t)s2 * 64 + lane * 2);
        ull v3 = *(const ull*)(P + (size_t)s3 * 64 + lane * 2);
        a0 = add2(a0, add2(v0, v1));
        a1 = add2(a1, add2(v2, v3));
    }
    for (; i < e; i++)
        a0 = add2(a0, *(const ull*)(P + (size_t)csr[i] * 64 + lane * 2));
    int deg = e - s;
    sc = 1.0f / (float)(deg > 1 ? deg : 1);
    return add2(a0, a1);
}

struct Gather3 {
    const float* PA[3]; const int* offA[3]; const int* csrA[3];
    const float* PB[3]; const int* offB[3]; const int* csrB[3];
    float* out[3]; int ws[4];
};

__global__ __launch_bounds__(256) void gather_all(Gather3 a) {
    int gw = (blockIdx.x * blockDim.x + threadIdx.x) >> 5;
    int lane = threadIdx.x & 31;
    if (gw >= a.ws[3]) return;
    int t = 0;
    while (gw >= a.ws[t + 1]) t++;
    int w = gw - a.ws[t];
    float scA, scB;
    ull accA = gather_rel(a.PA[t], a.offA[t], a.csrA[t], w, lane, scA);
    ull accB = gather_rel(a.PB[t], a.offB[t], a.csrB[t], w, lane, scB);
    ull res = add2(mul2(accA, splat2(scA)), mul2(accB, splat2(scB)));
    *(ull*)(a.out[t] + (size_t)w * 64 + lane * 2) = res;
}

// ---------------------------------------------------------------------------
// Shared GEMM tile core: acc += X[m0:m0+256, :ktiles*32] @ (wscale*(W0(+W1)))
// Block = 256 rows x 64 cols, 256 threads, 8x8 micro-tile, FFMA2 math.
// ---------------------------------------------------------------------------
__device__ __forceinline__ void gemm_tiles(
    const float* __restrict__ X, int ldx,
    const float* __restrict__ W0, const float* __restrict__ W1, float wscale,
    int ktiles, int m0, int M,
    float Xs[][33], float Ws[][72], ull acc[8][4]) {

    const int t = threadIdx.x;
    const int kq = t & 7;
    const int rowg = t >> 3;
    const int kw = t >> 3;
    const int cw = t & 7;
    const int cws = cw * 8 + ((cw >= 4) ? 4 : 0);
    const int rr = (t & 3) + ((t >> 5) << 2);
    const int r0 = rr * 8;
    const int cc = (t >> 2) & 7;
    const int c0s = cc * 8 + ((cc >= 4) ? 4 : 0);

    for (int kt = 0; kt < ktiles; kt++) {
        int kb = kt * 32;
        // ---- X tile ----
        #pragma unroll
        for (int it = 0; it < 8; it++) {
            int ml = rowg + 32 * it;
            int m = m0 + ml;
            float4 v = make_float4(0.f, 0.f, 0.f, 0.f);
            if (m < M) v = *(const float4*)(X + (size_t)m * ldx + kb + kq * 4);
            Xs[ml][kq * 4 + 0] = v.x;
            Xs[ml][kq * 4 + 1] = v.y;
            Xs[ml][kq * 4 + 2] = v.z;
            Xs[ml][kq * 4 + 3] = v.w;
        }
        // ---- W tile (optionally fused + scaled) ----
        {
            const float* wp = W0 + (size_t)(kb + kw) * 64 + cw * 8;
            float4 wa = *(const float4*)(wp);
            float4 wb = *(const float4*)(wp + 4);
            if (W1) {
                const float* wq = W1 + (size_t)(kb + kw) * 64 + cw * 8;
                float4 va = *(const float4*)(wq);
                float4 vb = *(const float4*)(wq + 4);
                wa.x += va.x; wa.y += va.y; wa.z += va.z; wa.w += va.w;
                wb.x += vb.x; wb.y += vb.y; wb.z += vb.z; wb.w += vb.w;
            }
            wa.x *= wscale; wa.y *= wscale; wa.z *= wscale; wa.w *= wscale;
            wb.x *= wscale; wb.y *= wscale; wb.z *= wscale; wb.w *= wscale;
            *(float4*)(&Ws[kw][cws]) = wa;
            *(float4*)(&Ws[kw][cws + 4]) = wb;
        }
        __syncthreads();

        #pragma unroll 8
        for (int k = 0; k < 32; k++) {
            ull a2[8];
            #pragma unroll
            for (int i = 0; i < 8; i++) a2[i] = splat2(Xs[r0 + i][k]);
            float4 bx = *(const float4*)(&Ws[k][c0s]);
            float4 by = *(const float4*)(&Ws[k][c0s + 4]);
            ull b2[4] = {pack2(bx.x, bx.y), pack2(bx.z, bx.w),
                         pack2(by.x, by.y), pack2(by.z, by.w)};
            #pragma unroll
            for (int i = 0; i < 8; i++)
                #pragma unroll
                for (int j = 0; j < 4; j++)
                    fma2(acc[i][j], a2[i], b2[j]);
        }
        __syncthreads();
    }
}

// ---------------------------------------------------------------------------
// proj_all: 6 independent projections Y[r] = X[r] @ W[r]
// ---------------------------------------------------------------------------
struct Proj6 { const float* X[6]; const float* W[6]; float* Y[6]; int M[6]; int bs[7]; };

template<int KT>
__global__ __launch_bounds__(256) void proj_all(Proj6 a) {
    __shared__ float Xs[256][33];
    __shared__ float Ws[32][72];
    int b = blockIdx.x, r = 0;
    while (b >= a.bs[r + 1]) r++;
    int m0 = (b - a.bs[r]) * 256;
    int M = a.M[r];

    ull acc[8][4];
    #pragma unroll
    for (int i = 0; i < 8; i++)
        #pragma unroll
        for (int j = 0; j < 4; j++) acc[i][j] = 0ull;

    gemm_tiles(a.X[r], KT * 32, a.W[r], nullptr, 1.0f, KT, m0, M, Xs, Ws, acc);

    const int t = threadIdx.x;
    const int rr = (t & 3) + ((t >> 5) << 2);
    const int r0 = rr * 8;
    const int c0 = ((t >> 2) & 7) * 8;
    float* Y = a.Y[r];
    #pragma unroll
    for (int i = 0; i < 8; i++) {
        int m = m0 + r0 + i;
        if (m >= M) break;
        float4 v0, v1;
        unpack2(acc[i][0], v0.x, v0.y);
        unpack2(acc[i][1], v0.z, v0.w);
        unpack2(acc[i][2], v1.x, v1.y);
        unpack2(acc[i][3], v1.z, v1.w);
        *(float4*)(Y + (size_t)m * 64 + c0) = v0;
        *(float4*)(Y + (size_t)m * 64 + c0 + 4) = v1;
    }
}

// ---------------------------------------------------------------------------
// combine1_all: H = relu(x @ 0.5(Wa+Wb) + 0.5*(AGG + ba + bb)) for 3 dst types
// ---------------------------------------------------------------------------
struct Comb3 {
    const float* X[3]; const float* Wa[3]; const float* Wb[3];
    const float* ba[3]; const float* bb[3]; const float* AGG[3];
    float* Y[3]; int M[3]; int bs[4];
};

__global__ __launch_bounds__(256) void combine1_all(Comb3 a) {
    __shared__ float Xs[256][33];
    __shared__ float Ws[32][72];
    int b = blockIdx.x, t3 = 0;
    while (b >= a.bs[t3 + 1]) t3++;
    int m0 = (b - a.bs[t3]) * 256;
    int M = a.M[t3];

    ull acc[8][4];
    #pragma unroll
    for (int i = 0; i < 8; i++)
        #pragma unroll
        for (int j = 0; j < 4; j++) acc[i][j] = 0ull;

    gemm_tiles(a.X[t3], 128, a.Wa[t3], a.Wb[t3], 0.5f, 4, m0, M, Xs, Ws, acc);

    const int t = threadIdx.x;
    const int rr = (t & 3) + ((t >> 5) << 2);
    const int r0 = rr * 8;
    const int c0 = ((t >> 2) & 7) * 8;
    const float* AGG = a.AGG[t3];
    float* Y = a.Y[t3];
    float cb[8];
    #pragma unroll
    for (int j = 0; j < 8; j++)
        cb[j] = 0.5f * (a.ba[t3][c0 + j] + a.bb[t3][c0 + j]);

    #pragma unroll
    for (int i = 0; i < 8; i++) {
        int m = m0 + r0 + i;
        if (m >= M) break;
        size_t base = (size_t)m * 64;
        float4 g0 = *(const float4*)(AGG + base + c0);
        float4 g1 = *(const float4*)(AGG + base + c0 + 4);
        float av[8];
        unpack2(acc[i][0], av[0], av[1]);
        unpack2(acc[i][1], av[2], av[3]);
        unpack2(acc[i][2], av[4], av[5]);
        unpack2(acc[i][3], av[6], av[7]);
        float gg[8] = {g0.x, g0.y, g0.z, g0.w, g1.x, g1.y, g1.z, g1.w};
        float4 o0, o1;
        float* oo[8] = {&o0.x, &o0.y, &o0.z, &o0.w, &o1.x, &o1.y, &o1.z, &o1.w};
        #pragma unroll
        for (int j = 0; j < 8; j++)
            *oo[j] = fmaxf(av[j] + 0.5f * gg[j] + cb[j], 0.0f);
        *(float4*)(Y + base + c0) = o0;
        *(float4*)(Y + base + c0 + 4) = o1;
    }
}

// ---------------------------------------------------------------------------
// final_all: O = l2norm( H @ 0.5(W2a+W2b) + 0.5*(AGG2 + b2a + b2b)
//                        + x @ Wres + bres )   for 3 dst types
// ---------------------------------------------------------------------------
struct Final3 {
    const float* Hs[3]; const float* W2a[3]; const float* W2b[3];
    const float* b2a[3]; const float* b2b[3]; const float* AGG[3];
    const float* Xr[3]; const float* Wr[3]; const float* br[3];
    float* Y[3]; int M[3]; int bs[4];
};

__global__ __launch_bounds__(256) void final_all(Final3 a) {
    __shared__ float Xs[256][33];
    __shared__ float Ws[32][72];
    int b = blockIdx.x, t3 = 0;
    while (b >= a.bs[t3 + 1]) t3++;
    int m0 = (b - a.bs[t3]) * 256;
    int M = a.M[t3];

    ull acc[8][4];
    #pragma unroll
    for (int i = 0; i < 8; i++)
        #pragma unroll
        for (int j = 0; j < 4; j++) acc[i][j] = 0ull;

    // layer-2 combine GEMM (K=64, 0.5-scaled fused weights)
    gemm_tiles(a.Hs[t3], 64, a.W2a[t3], a.W2b[t3], 0.5f, 2, m0, M, Xs, Ws, acc);
    // residual GEMM (K=128), continues the same accumulator
    gemm_tiles(a.Xr[t3], 128, a.Wr[t3], nullptr, 1.0f, 4, m0, M, Xs, Ws, acc);

    const int t = threadIdx.x;
    const int rr = (t & 3) + ((t >> 5) << 2);
    const int r0 = rr * 8;
    const int c0 = ((t >> 2) & 7) * 8;
    const float* AGG = a.AGG[t3];
    float* Y = a.Y[t3];
    float cb[8];
    #pragma unroll
    for (int j = 0; j < 8; j++)
        cb[j] = 0.5f * (a.b2a[t3][c0 + j] + a.b2b[t3][c0 + j]) + a.br[t3][c0 + j];

    #pragma unroll
    for (int i = 0; i < 8; i++) {   // no break: all lanes run the shuffles
        int m = m0 + r0 + i;
        bool ok = (m < M);
        size_t base = (size_t)m * 64;
        float v[8];
        if (ok) {
            float4 g0 = *(const float4*)(AGG + base + c0);
            float4 g1 = *(const float4*)(AGG + base + c0 + 4);
            float av[8];
            unpack2(acc[i][0], av[0], av[1]);
            unpack2(acc[i][1], av[2], av[3]);
            unpack2(acc[i][2], av[4], av[5]);
            unpack2(acc[i][3], av[6], av[7]);
            float gg[8] = {g0.x, g0.y, g0.z, g0.w, g1.x, g1.y, g1.z, g1.w};
            #pragma unroll
            for (int j = 0; j < 8; j++) v[j] = av[j] + 0.5f * gg[j] + cb[j];
        } else {
            #pragma unroll
            for (int j = 0; j < 8; j++) v[j] = 0.f;
        }
        // row L2 norm: reduce over the 8 threads sharing this row (lane bits 2-4)
        float ss = 0.f;
        #pragma unroll
        for (int j = 0; j < 8; j++) ss += v[j] * v[j];
        ss += __shfl_xor_sync(0xffffffffu, ss, 4);
        ss += __shfl_xor_sync(0xffffffffu, ss, 8);
        ss += __shfl_xor_sync(0xffffffffu, ss, 16);
        if (ok) {
            float inv = 1.0f / fmaxf(sqrtf(ss), 1e-12f);
            float4 o0 = make_float4(v[0] * inv, v[1] * inv, v[2] * inv, v[3] * inv);
            float4 o1 = make_float4(v[4] * inv, v[5] * inv, v[6] * inv, v[7] * inv);
            *(float4*)(Y + base + c0) = o0;
            *(float4*)(Y + base + c0 + 4) = o1;
        }
    }
}

// ---------------------------------------------------------------------------
// Host orchestration
// ---------------------------------------------------------------------------
extern "C" void kernel_launch(void* const* d_in, const int* in_sizes, int n_in,
                              void* d_out, int out_size) {
    const float* xc = (const float*)d_in[0];
    const float* xm = (const float*)d_in[1];
    const float* xd = (const float*)d_in[2];
    // relation order: 0=c->m, 1=m->d, 2=c->d, 3=m->c, 4=d->m, 5=d->c
    const int srcIdx[6] = {3, 5, 7, 9, 11, 13};
    const int dstIdx[6] = {4, 6, 8, 10, 12, 14};
    const int* SRC[6]; const int* DST[6]; int EE[6];
    for (int r = 0; r < 6; r++) {
        SRC[r] = (const int*)d_in[srcIdx[r]];
        DST[r] = (const int*)d_in[dstIdx[r]];
        EE[r]  = in_sizes[srcIdx[r]];
    }
    const float* W1l  = (const float*)d_in[15];
    const float* W1r  = (const float*)d_in[16];
    const float* b1   = (const float*)d_in[17];
    const float* W2l  = (const float*)d_in[18];
    const float* W2r  = (const float*)d_in[19];
    const float* b2   = (const float*)d_in[20];
    const float* Wres = (const float*)d_in[21];
    const float* bres = (const float*)d_in[22];
    float* out = (float*)d_out;

    const int NSRC[6]    = {NC, NM, NC, NM, ND, ND};
    const int NDSTA[6]   = {NM, ND, ND, NC, NM, NC};
    const int srcType[6] = {0, 1, 0, 1, 2, 2};  // 0=c,1=m,2=d

    float* S = nullptr;
    cudaGetSymbolAddress((void**)&S, g_scratch);

    int*   OFF = (int*)S;
    int*   CUR = OFF + OFF_WORDS;
    int*   CSR = CUR + CUR_WORDS;
    float* P   = (float*)(CSR + CSR_WORDS);
    float* AGG = P + P_WORDS;
    float* H   = AGG + AGG_WORDS;

    int* offR[6]; int* curR[6]; int* csrR[6]; float* PR[6];
    {
        size_t o = 0, c = 0, e = 0, p = 0;
        for (int r = 0; r < 6; r++) {
            offR[r] = OFF + o;  o += (size_t)NDSTA[r] + 1;
            curR[r] = CUR + c;  c += (size_t)NDSTA[r];
            csrR[r] = CSR + e;  e += (size_t)EE[r];
            PR[r]   = P + p;    p += (size_t)NSRC[r] * 64;
        }
    }

    float* AGGm = AGG;
    float* AGGd = AGGm + (size_t)NM * 64;
    float* AGGc = AGGd + (size_t)ND * 64;
    float* Hc = H;
    float* Hm = Hc + (size_t)NC * 64;
    float* Hd = Hm + (size_t)NM * 64;
    const float* X1[3] = {xc, xm, xd};
    const float* HX[3] = {Hc, Hm, Hd};
    float* Oc = out;
    float* Om = Oc + (size_t)NC * 64;
    float* Od = Om + (size_t)NM * 64;

    // ---- CSR build (3 fused launches + zero) ----
    {
        int nz = (int)(OFF_WORDS + CUR_WORDS);
        zero_int_kernel<<<(nz + 255) / 256, 256>>>(OFF, nz);
    }
    Edge6 ea;
    {
        int cum = 0;
        for (int r = 0; r < 6; r++) {
            ea.src[r] = SRC[r]; ea.dst[r] = DST[r];
            ea.cnt[r] = offR[r]; ea.cur[r] = curR[r]; ea.csr[r] = csrR[r];
            ea.E[r] = EE[r];
            ea.bs[r] = cum; cum += (EE[r] + 255) / 256;
        }
        ea.bs[6] = cum;
    }
    count_all<<<ea.bs[6], 256>>>(ea);
    {
        ScanArgs sa;
        for (int r = 0; r < 6; r++) { sa.data[r] = offR[r]; sa.n[r] = NDSTA[r]; }
        scan6<<<6, 1024>>>(sa);
    }
    fill_all<<<ea.bs[6], 256>>>(ea);

    // ---- shared gather descriptor (relation pairing per dst type) ----
    // t=0: m <- (rel0 from c, rel4 from d); t=1: d <- (rel1, rel2); t=2: c <- (rel3, rel5)
    const int relA[3] = {0, 1, 3};
    const int relB[3] = {4, 2, 5};
    float* AGGt[3] = {AGGm, AGGd, AGGc};
    const int NT[3] = {NM, ND, NC};
    Gather3 ga;
    {
        int cum = 0;
        for (int t = 0; t < 3; t++) {
            ga.offA[t] = offR[relA[t]]; ga.csrA[t] = csrR[relA[t]];
            ga.offB[t] = offR[relB[t]]; ga.csrB[t] = csrR[relB[t]];
            ga.out[t] = AGGt[t];
            ga.ws[t] = cum; cum += NT[t];
        }
        ga.ws[3] = cum;
    }
    const int gatherBlocks = ((NM + ND + NC) * 32 + 255) / 256;

    // ---- layer 1: projections (1 launch) ----
    Proj6 p1;
    {
        int cum = 0;
        for (int r = 0; r < 6; r++) {
            p1.X[r] = X1[srcType[r]];
            p1.W[r] = W1l + (size_t)r * 8192;
            p1.Y[r] = PR[r];
            p1.M[r] = NSRC[r];
            p1.bs[r] = cum; cum += (NSRC[r] + 255) / 256;
        }
        p1.bs[6] = cum;
    }
    proj_all<4><<<p1.bs[6], 256>>>(p1);

    // ---- layer 1: gathers (1 launch) ----
    for (int t = 0; t < 3; t++) { ga.PA[t] = PR[relA[t]]; ga.PB[t] = PR[relB[t]]; }
    gather_all<<<gatherBlocks, 256>>>(ga);

    // ---- layer 1: combines (1 launch) ----
    const float* XD[3] = {xm, xd, xc};
    float* HT[3] = {Hm, Hd, Hc};
    Comb3 c1;
    {
        int cum = 0;
        for (int t = 0; t < 3; t++) {
            c1.X[t]  = XD[t];
            c1.Wa[t] = W1r + (size_t)relA[t] * 8192;
            c1.Wb[t] = W1r + (size_t)relB[t] * 8192;
            c1.ba[t] = b1 + (size_t)relA[t] * 64;
            c1.bb[t] = b1 + (size_t)relB[t] * 64;
            c1.AGG[t] = AGGt[t];
            c1.Y[t] = HT[t];
            c1.M[t] = NT[t];
            c1.bs[t] = cum; cum += (NT[t] + 255) / 256;
        }
        c1.bs[3] = cum;
    }
    combine1_all<<<c1.bs[3], 256>>>(c1);

    // ---- layer 2: projections (1 launch) ----
    Proj6 p2;
    {
        int cum = 0;
        for (int r = 0; r < 6; r++) {
            p2.X[r] = HX[srcType[r]];
            p2.W[r] = W2l + (size_t)r * 4096;
            p2.Y[r] = PR[r];
            p2.M[r] = NSRC[r];
            p2.bs[r] = cum; cum += (NSRC[r] + 255) / 256;
        }
        p2.bs[6] = cum;
    }
    proj_all<2><<<p2.bs[6], 256>>>(p2);

    // ---- layer 2: gathers (1 launch) ----
    gather_all<<<gatherBlocks, 256>>>(ga);

    // ---- final: combine2 + residual + l2norm (1 launch) ----
    const float* HDst[3] = {Hm, Hd, Hc};
    const float* XRes[3] = {xm, xd, xc};
    const int resIdx[3] = {1, 2, 0};  // W_res rows: 0=c,1=m,2=d
    float* OT[3] = {Om, Od, Oc};
    Final3 f;
    {
        int cum = 0;
        for (int t = 0; t < 3; t++) {
            f.Hs[t]  = HDst[t];
            f.W2a[t] = W2r + (size_t)relA[t] * 4096;
            f.W2b[t] = W2r + (size_t)relB[t] * 4096;
            f.b2a[t] = b2 + (size_t)relA[t] * 64;
            f.b2b[t] = b2 + (size_t)relB[t] * 64;
            f.AGG[t] = AGGt[t];
            f.Xr[t]  = XRes[t];
            f.Wr[t]  = Wres + (size_t)resIdx[t] * 8192;
            f.br[t]  = bres + (size_t)resIdx[t] * 64;
            f.Y[t] = OT[t];
            f.M[t] = NT[t];
            f.bs[t] = cum; cum += (NT[t] + 255) / 256;
        }
        f.bs[3] = cum;
    }
    final_all<<<f.bs[3], 256>>>(f);
}

// round 5
// speedup vs baseline: 1.5160x; 1.0570x over previous
#include <cuda_runtime.h>
#include <cuda_fp16.h>
#include <cstddef>
#include <cstdint>

typedef unsigned long long ull;

// ---------------------------------------------------------------------------
// Problem constants
// ---------------------------------------------------------------------------
#define NC 100000
#define NM 50000
#define ND 10000

// Scratch layout (4-byte words, every region base 16B-aligned):
//   OFF : 320,008    (per-relation CSR exclusive offsets, NDST+1 each; padded)
//   CSR : 4,800,000  (edge src ids grouped by dst, per relation)
//   P   : 10,240,000 (per-relation projected source features, fp16, 320k x 64)
//   AGG : 10,240,000 (merged per-dst-type aggregated means, fp32, 160k x 64)
//   H   : 10,240,000 (layer-1 hidden states, fp32)
#define OFF_WORDS 320008ull
#define CSR_WORDS 4800000ull
#define P_WORDS   10240000ull
#define AGG_WORDS 10240000ull
#define H_WORDS   10240000ull
#define SCRATCH_WORDS (OFF_WORDS + CSR_WORDS + P_WORDS + AGG_WORDS + H_WORDS)
__device__ __align__(16) float g_scratch[SCRATCH_WORDS];

// ---------------------------------------------------------------------------
// f32x2 packed helpers (Blackwell FFMA2 path: 2x fp32 FMA throughput)
// ---------------------------------------------------------------------------
__device__ __forceinline__ ull splat2(float x) {
    ull r; asm("mov.b64 %0, {%1, %1};" : "=l"(r) : "f"(x)); return r;
}
__device__ __forceinline__ ull pack2(float lo, float hi) {
    ull r; asm("mov.b64 %0, {%1, %2};" : "=l"(r) : "f"(lo), "f"(hi)); return r;
}
__device__ __forceinline__ void unpack2(ull v, float& lo, float& hi) {
    asm("mov.b64 {%0, %1}, %2;" : "=f"(lo), "=f"(hi) : "l"(v));
}
__device__ __forceinline__ void fma2(ull& d, ull a, ull b) {
    asm("fma.rn.f32x2 %0, %1, %2, %0;" : "+l"(d) : "l"(a), "l"(b));
}
__device__ __forceinline__ ull add2(ull a, ull b) {
    ull r; asm("add.rn.f32x2 %0, %1, %2;" : "=l"(r) : "l"(a), "l"(b)); return r;
}
__device__ __forceinline__ ull mul2(ull a, ull b) {
    ull r; asm("mul.rn.f32x2 %0, %1, %2;" : "=l"(r) : "l"(a), "l"(b)); return r;
}
// half2 (as uint) -> packed f32x2
__device__ __forceinline__ ull h2_to_f2(unsigned int h) {
    __half2 hv = *reinterpret_cast<__half2*>(&h);
    float2 f = __half22float2(hv);
    return pack2(f.x, f.y);
}

// ---------------------------------------------------------------------------
// CSR build kernels (all relations fused per kernel)
// ---------------------------------------------------------------------------
__global__ void zero_int_kernel(int* __restrict__ p, int n) {
    int i = blockIdx.x * blockDim.x + threadIdx.x;
    if (i < n) p[i] = 0;
}

struct Edge6 {
    const int* src[6]; const int* dst[6];
    int* off[6]; int* csr[6];
    int bs[7]; int E[6];
};

__global__ void count_all(Edge6 a) {
    int b = blockIdx.x, r = 0;
    while (b >= a.bs[r + 1]) r++;
    int e = (b - a.bs[r]) * 256 + threadIdx.x;
    if (e < a.E[r]) atomicAdd(&a.off[r][a.dst[r][e] + 1], 1);
}

// Cursor-free fill: consumes the exclusive offsets in-place.
// After this kernel, off[d] == original off[d+1] (segment end).
__global__ void fill_all(Edge6 a) {
    int b = blockIdx.x, r = 0;
    while (b >= a.bs[r + 1]) r++;
    int e = (b - a.bs[r]) * 256 + threadIdx.x;
    if (e < a.E[r]) {
        int d = a.dst[r][e];
        int p = atomicAdd(&a.off[r][d], 1);
        a.csr[r][p] = a.src[r][e];
    }
}

struct ScanArgs { int* data[6]; int n[6]; };

// One block per relation; inclusive scan of data[0..n] via warp shuffles.
__global__ __launch_bounds__(1024) void scan6(ScanArgs a) {
    __shared__ int wsum[33];
    int* data = a.data[blockIdx.x];
    int n = a.n[blockIdx.x];
    int t = threadIdx.x, lane = t & 31, wid = t >> 5;
    int carry = 0;
    for (int base = 0; base <= n; base += 4096) {
        int i0 = base + t * 4;
        int v0 = (i0     <= n) ? data[i0]     : 0;
        int v1 = (i0 + 1 <= n) ? data[i0 + 1] : 0;
        int v2 = (i0 + 2 <= n) ? data[i0 + 2] : 0;
        int v3 = (i0 + 3 <= n) ? data[i0 + 3] : 0;
        int s01 = v0 + v1;
        int s = s01 + v2 + v3;
        int sc = s;
        #pragma unroll
        for (int o = 1; o < 32; o <<= 1) {
            int u = __shfl_up_sync(0xffffffffu, sc, o);
            if (lane >= o) sc += u;
        }
        if (lane == 31) wsum[wid] = sc;
        __syncthreads();
        if (wid == 0) {
            int w = wsum[lane];
            int wc = w;
            #pragma unroll
            for (int o = 1; o < 32; o <<= 1) {
                int u = __shfl_up_sync(0xffffffffu, wc, o);
                if (lane >= o) wc += u;
            }
            wsum[lane] = wc;
            if (lane == 31) wsum[32] = wc;
        }
        __syncthreads();
        int prefix = carry + (wid ? wsum[wid - 1] : 0) + (sc - s);
        if (i0     <= n) data[i0]     = prefix + v0;
        if (i0 + 1 <= n) data[i0 + 1] = prefix + s01;
        if (i0 + 2 <= n) data[i0 + 2] = prefix + s01 + v2;
        if (i0 + 3 <= n) data[i0 + 3] = prefix + s;
        carry += wsum[32];
        __syncthreads();
    }
}

// ---------------------------------------------------------------------------
// Merged dual-relation gather (fp16 source rows): one warp per dst node.
// Each lane owns 2 consecutive columns (one half2 = 4B load per edge).
// Offsets are post-fill: segment of w is [w? off[w-1] : 0, off[w]).
// ---------------------------------------------------------------------------
__device__ __forceinline__ ull gather_rel(const __half* __restrict__ P,
                                          const int* __restrict__ off,
                                          const int* __restrict__ csr,
                                          int w, int lane, float& sc) {
    int s = w ? off[w - 1] : 0;
    int e = off[w];
    const unsigned int* B = (const unsigned int*)P + lane;  // row stride 32 uints
    ull a0 = 0ull, a1 = 0ull;
    int i = s;
    for (; i + 4 <= e; i += 4) {
        int s0 = csr[i], s1 = csr[i + 1], s2 = csr[i + 2], s3 = csr[i + 3];
        unsigned int v0 = B[(size_t)s0 * 32];
        unsigned int v1 = B[(size_t)s1 * 32];
        unsigned int v2 = B[(size_t)s2 * 32];
        unsigned int v3 = B[(size_t)s3 * 32];
        a0 = add2(a0, add2(h2_to_f2(v0), h2_to_f2(v1)));
        a1 = add2(a1, add2(h2_to_f2(v2), h2_to_f2(v3)));
    }
    for (; i < e; i++)
        a0 = add2(a0, h2_to_f2(B[(size_t)csr[i] * 32]));
    int deg = e - s;
    sc = 1.0f / (float)(deg > 1 ? deg : 1);
    return add2(a0, a1);
}

struct Gather3 {
    const __half* PA[3]; const int* offA[3]; const int* csrA[3];
    const __half* PB[3]; const int* offB[3]; const int* csrB[3];
    float* out[3]; int ws[4];
};

__global__ __launch_bounds__(256) void gather_all(Gather3 a) {
    int gw = (blockIdx.x * blockDim.x + threadIdx.x) >> 5;
    int lane = threadIdx.x & 31;
    if (gw >= a.ws[3]) return;
    int t = 0;
    while (gw >= a.ws[t + 1]) t++;
    int w = gw - a.ws[t];
    float scA, scB;
    ull accA = gather_rel(a.PA[t], a.offA[t], a.csrA[t], w, lane, scA);
    ull accB = gather_rel(a.PB[t], a.offB[t], a.csrB[t], w, lane, scB);
    ull res = add2(mul2(accA, splat2(scA)), mul2(accB, splat2(scB)));
    *(ull*)(a.out[t] + (size_t)w * 64 + lane * 2) = res;
}

// ---------------------------------------------------------------------------
// Shared GEMM tile core: acc += X[m0:m0+256, :ktiles*32] @ (wscale*(W0(+W1)))
// Block = 256 rows x 64 cols, 256 threads, 8x8 micro-tile, FFMA2 math.
// ---------------------------------------------------------------------------
__device__ __forceinline__ void gemm_tiles(
    const float* __restrict__ X, int ldx,
    const float* __restrict__ W0, const float* __restrict__ W1, float wscale,
    int ktiles, int m0, int M,
    float Xs[][33], float Ws[][72], ull acc[8][4]) {

    const int t = threadIdx.x;
    const int kq = t & 7;
    const int rowg = t >> 3;
    const int kw = t >> 3;
    const int cw = t & 7;
    const int cws = cw * 8 + ((cw >= 4) ? 4 : 0);
    const int rr = (t & 3) + ((t >> 5) << 2);
    const int r0 = rr * 8;
    const int cc = (t >> 2) & 7;
    const int c0s = cc * 8 + ((cc >= 4) ? 4 : 0);

    for (int kt = 0; kt < ktiles; kt++) {
        int kb = kt * 32;
        // ---- X tile ----
        #pragma unroll
        for (int it = 0; it < 8; it++) {
            int ml = rowg + 32 * it;
            int m = m0 + ml;
            float4 v = make_float4(0.f, 0.f, 0.f, 0.f);
            if (m < M) v = *(const float4*)(X + (size_t)m * ldx + kb + kq * 4);
            Xs[ml][kq * 4 + 0] = v.x;
            Xs[ml][kq * 4 + 1] = v.y;
            Xs[ml][kq * 4 + 2] = v.z;
            Xs[ml][kq * 4 + 3] = v.w;
        }
        // ---- W tile (optionally fused + scaled) ----
        {
            const float* wp = W0 + (size_t)(kb + kw) * 64 + cw * 8;
            float4 wa = *(const float4*)(wp);
            float4 wb = *(const float4*)(wp + 4);
            if (W1) {
                const float* wq = W1 + (size_t)(kb + kw) * 64 + cw * 8;
                float4 va = *(const float4*)(wq);
                float4 vb = *(const float4*)(wq + 4);
                wa.x += va.x; wa.y += va.y; wa.z += va.z; wa.w += va.w;
                wb.x += vb.x; wb.y += vb.y; wb.z += vb.z; wb.w += vb.w;
            }
            wa.x *= wscale; wa.y *= wscale; wa.z *= wscale; wa.w *= wscale;
            wb.x *= wscale; wb.y *= wscale; wb.z *= wscale; wb.w *= wscale;
            *(float4*)(&Ws[kw][cws]) = wa;
            *(float4*)(&Ws[kw][cws + 4]) = wb;
        }
        __syncthreads();

        #pragma unroll 8
        for (int k = 0; k < 32; k++) {
            ull a2[8];
            #pragma unroll
            for (int i = 0; i < 8; i++) a2[i] = splat2(Xs[r0 + i][k]);
            float4 bx = *(const float4*)(&Ws[k][c0s]);
            float4 by = *(const float4*)(&Ws[k][c0s + 4]);
            ull b2[4] = {pack2(bx.x, bx.y), pack2(bx.z, bx.w),
                         pack2(by.x, by.y), pack2(by.z, by.w)};
            #pragma unroll
            for (int i = 0; i < 8; i++)
                #pragma unroll
                for (int j = 0; j < 4; j++)
                    fma2(acc[i][j], a2[i], b2[j]);
        }
        __syncthreads();
    }
}

// ---------------------------------------------------------------------------
// proj_all: 6 independent projections Y[r] = fp16(X[r] @ W[r])
// ---------------------------------------------------------------------------
struct Proj6 { const float* X[6]; const float* W[6]; __half* Y[6]; int M[6]; int bs[7]; };

template<int KT>
__global__ __launch_bounds__(256) void proj_all(Proj6 a) {
    __shared__ float Xs[256][33];
    __shared__ float Ws[32][72];
    int b = blockIdx.x, r = 0;
    while (b >= a.bs[r + 1]) r++;
    int m0 = (b - a.bs[r]) * 256;
    int M = a.M[r];

    ull acc[8][4];
    #pragma unroll
    for (int i = 0; i < 8; i++)
        #pragma unroll
        for (int j = 0; j < 4; j++) acc[i][j] = 0ull;

    gemm_tiles(a.X[r], KT * 32, a.W[r], nullptr, 1.0f, KT, m0, M, Xs, Ws, acc);

    const int t = threadIdx.x;
    const int rr = (t & 3) + ((t >> 5) << 2);
    const int r0 = rr * 8;
    const int c0 = ((t >> 2) & 7) * 8;
    __half* Y = a.Y[r];
    #pragma unroll
    for (int i = 0; i < 8; i++) {
        int m = m0 + r0 + i;
        if (m >= M) break;
        float av[8];
        unpack2(acc[i][0], av[0], av[1]);
        unpack2(acc[i][1], av[2], av[3]);
        unpack2(acc[i][2], av[4], av[5]);
        unpack2(acc[i][3], av[6], av[7]);
        __half2 h0 = __floats2half2_rn(av[0], av[1]);
        __half2 h1 = __floats2half2_rn(av[2], av[3]);
        __half2 h2 = __floats2half2_rn(av[4], av[5]);
        __half2 h3 = __floats2half2_rn(av[6], av[7]);
        uint4 st;
        st.x = *(unsigned int*)&h0;
        st.y = *(unsigned int*)&h1;
        st.z = *(unsigned int*)&h2;
        st.w = *(unsigned int*)&h3;
        *(uint4*)(Y + (size_t)m * 64 + c0) = st;
    }
}

// ---------------------------------------------------------------------------
// combine1_all: H = relu(x @ 0.5(Wa+Wb) + 0.5*(AGG + ba + bb)) for 3 dst types
// ---------------------------------------------------------------------------
struct Comb3 {
    const float* X[3]; const float* Wa[3]; const float* Wb[3];
    const float* ba[3]; const float* bb[3]; const float* AGG[3];
    float* Y[3]; int M[3]; int bs[4];
};

__global__ __launch_bounds__(256) void combine1_all(Comb3 a) {
    __shared__ float Xs[256][33];
    __shared__ float Ws[32][72];
    int b = blockIdx.x, t3 = 0;
    while (b >= a.bs[t3 + 1]) t3++;
    int m0 = (b - a.bs[t3]) * 256;
    int M = a.M[t3];

    ull acc[8][4];
    #pragma unroll
    for (int i = 0; i < 8; i++)
        #pragma unroll
        for (int j = 0; j < 4; j++) acc[i][j] = 0ull;

    gemm_tiles(a.X[t3], 128, a.Wa[t3], a.Wb[t3], 0.5f, 4, m0, M, Xs, Ws, acc);

    const int t = threadIdx.x;
    const int rr = (t & 3) + ((t >> 5) << 2);
    const int r0 = rr * 8;
    const int c0 = ((t >> 2) & 7) * 8;
    const float* AGG = a.AGG[t3];
    float* Y = a.Y[t3];
    float cb[8];
    #pragma unroll
    for (int j = 0; j < 8; j++)
        cb[j] = 0.5f * (a.ba[t3][c0 + j] + a.bb[t3][c0 + j]);

    #pragma unroll
    for (int i = 0; i < 8; i++) {
        int m = m0 + r0 + i;
        if (m >= M) break;
        size_t base = (size_t)m * 64;
        float4 g0 = *(const float4*)(AGG + base + c0);
        float4 g1 = *(const float4*)(AGG + base + c0 + 4);
        float av[8];
        unpack2(acc[i][0], av[0], av[1]);
        unpack2(acc[i][1], av[2], av[3]);
        unpack2(acc[i][2], av[4], av[5]);
        unpack2(acc[i][3], av[6], av[7]);
        float gg[8] = {g0.x, g0.y, g0.z, g0.w, g1.x, g1.y, g1.z, g1.w};
        float4 o0, o1;
        float* oo[8] = {&o0.x, &o0.y, &o0.z, &o0.w, &o1.x, &o1.y, &o1.z, &o1.w};
        #pragma unroll
        for (int j = 0; j < 8; j++)
            *oo[j] = fmaxf(av[j] + 0.5f * gg[j] + cb[j], 0.0f);
        *(float4*)(Y + base + c0) = o0;
        *(float4*)(Y + base + c0 + 4) = o1;
    }
}

// ---------------------------------------------------------------------------
// final_all: O = l2norm( H @ 0.5(W2a+W2b) + 0.5*(AGG2 + b2a + b2b)
//                        + x @ Wres + bres )   for 3 dst types
// ---------------------------------------------------------------------------
struct Final3 {
    const float* Hs[3]; const float* W2a[3]; const float* W2b[3];
    const float* b2a[3]; const float* b2b[3]; const float* AGG[3];
    const float* Xr[3]; const float* Wr[3]; const float* br[3];
    float* Y[3]; int M[3]; int bs[4];
};

__global__ __launch_bounds__(256) void final_all(Final3 a) {
    __shared__ float Xs[256][33];
    __shared__ float Ws[32][72];
    int b = blockIdx.x, t3 = 0;
    while (b >= a.bs[t3 + 1]) t3++;
    int m0 = (b - a.bs[t3]) * 256;
    int M = a.M[t3];

    ull acc[8][4];
    #pragma unroll
    for (int i = 0; i < 8; i++)
        #pragma unroll
        for (int j = 0; j < 4; j++) acc[i][j] = 0ull;

    // layer-2 combine GEMM (K=64, 0.5-scaled fused weights)
    gemm_tiles(a.Hs[t3], 64, a.W2a[t3], a.W2b[t3], 0.5f, 2, m0, M, Xs, Ws, acc);
    // residual GEMM (K=128), continues the same accumulator
    gemm_tiles(a.Xr[t3], 128, a.Wr[t3], nullptr, 1.0f, 4, m0, M, Xs, Ws, acc);

    const int t = threadIdx.x;
    const int rr = (t & 3) + ((t >> 5) << 2);
    const int r0 = rr * 8;
    const int c0 = ((t >> 2) & 7) * 8;
    const float* AGG = a.AGG[t3];
    float* Y = a.Y[t3];
    float cb[8];
    #pragma unroll
    for (int j = 0; j < 8; j++)
        cb[j] = 0.5f * (a.b2a[t3][c0 + j] + a.b2b[t3][c0 + j]) + a.br[t3][c0 + j];

    #pragma unroll
    for (int i = 0; i < 8; i++) {   // no break: all lanes run the shuffles
        int m = m0 + r0 + i;
        bool ok = (m < M);
        size_t base = (size_t)m * 64;
        float v[8];
        if (ok) {
            float4 g0 = *(const float4*)(AGG + base + c0);
            float4 g1 = *(const float4*)(AGG + base + c0 + 4);
            float av[8];
            unpack2(acc[i][0], av[0], av[1]);
            unpack2(acc[i][1], av[2], av[3]);
            unpack2(acc[i][2], av[4], av[5]);
            unpack2(acc[i][3], av[6], av[7]);
            float gg[8] = {g0.x, g0.y, g0.z, g0.w, g1.x, g1.y, g1.z, g1.w};
            #pragma unroll
            for (int j = 0; j < 8; j++) v[j] = av[j] + 0.5f * gg[j] + cb[j];
        } else {
            #pragma unroll
            for (int j = 0; j < 8; j++) v[j] = 0.f;
        }
        // row L2 norm: reduce over the 8 threads sharing this row (lane bits 2-4)
        float ss = 0.f;
        #pragma unroll
        for (int j = 0; j < 8; j++) ss += v[j] * v[j];
        ss += __shfl_xor_sync(0xffffffffu, ss, 4);
        ss += __shfl_xor_sync(0xffffffffu, ss, 8);
        ss += __shfl_xor_sync(0xffffffffu, ss, 16);
        if (ok) {
            float inv = 1.0f / fmaxf(sqrtf(ss), 1e-12f);
            float4 o0 = make_float4(v[0] * inv, v[1] * inv, v[2] * inv, v[3] * inv);
            float4 o1 = make_float4(v[4] * inv, v[5] * inv, v[6] * inv, v[7] * inv);
            *(float4*)(Y + base + c0) = o0;
            *(float4*)(Y + base + c0 + 4) = o1;
        }
    }
}

// ---------------------------------------------------------------------------
// Host orchestration
// ---------------------------------------------------------------------------
extern "C" void kernel_launch(void* const* d_in, const int* in_sizes, int n_in,
                              void* d_out, int out_size) {
    const float* xc = (const float*)d_in[0];
    const float* xm = (const float*)d_in[1];
    const float* xd = (const float*)d_in[2];
    // relation order: 0=c->m, 1=m->d, 2=c->d, 3=m->c, 4=d->m, 5=d->c
    const int srcIdx[6] = {3, 5, 7, 9, 11, 13};
    const int dstIdx[6] = {4, 6, 8, 10, 12, 14};
    const int* SRC[6]; const int* DST[6]; int EE[6];
    for (int r = 0; r < 6; r++) {
        SRC[r] = (const int*)d_in[srcIdx[r]];
        DST[r] = (const int*)d_in[dstIdx[r]];
        EE[r]  = in_sizes[srcIdx[r]];
    }
    const float* W1l  = (const float*)d_in[15];
    const float* W1r  = (const float*)d_in[16];
    const float* b1   = (const float*)d_in[17];
    const float* W2l  = (const float*)d_in[18];
    const float* W2r  = (const float*)d_in[19];
    const float* b2   = (const float*)d_in[20];
    const float* Wres = (const float*)d_in[21];
    const float* bres = (const float*)d_in[22];
    float* out = (float*)d_out;

    const int NSRC[6]    = {NC, NM, NC, NM, ND, ND};
    const int NDSTA[6]   = {NM, ND, ND, NC, NM, NC};
    const int srcType[6] = {0, 1, 0, 1, 2, 2};  // 0=c,1=m,2=d

    float* S = nullptr;
    cudaGetSymbolAddress((void**)&S, g_scratch);

    int*    OFF = (int*)S;
    int*    CSR = OFF + OFF_WORDS;
    __half* P   = (__half*)(CSR + CSR_WORDS);
    float*  AGG = (float*)(CSR + CSR_WORDS) + P_WORDS;
    float*  H   = AGG + AGG_WORDS;

    int* offR[6]; int* csrR[6]; __half* PR[6];
    {
        size_t o = 0, e = 0, p = 0;
        for (int r = 0; r < 6; r++) {
            offR[r] = OFF + o;  o += (size_t)NDSTA[r] + 1;
            csrR[r] = CSR + e;  e += (size_t)EE[r];
            PR[r]   = P + p;    p += (size_t)NSRC[r] * 64;
        }
    }

    float* AGGm = AGG;
    float* AGGd = AGGm + (size_t)NM * 64;
    float* AGGc = AGGd + (size_t)ND * 64;
    float* Hc = H;
    float* Hm = Hc + (size_t)NC * 64;
    float* Hd = Hm + (size_t)NM * 64;
    const float* X1[3] = {xc, xm, xd};
    const float* HX[3] = {Hc, Hm, Hd};
    float* Oc = out;
    float* Om = Oc + (size_t)NC * 64;
    float* Od = Om + (size_t)NM * 64;

    // ---- CSR build ----
    {
        int nz = (int)OFF_WORDS;
        zero_int_kernel<<<(nz + 255) / 256, 256>>>(OFF, nz);
    }
    Edge6 ea;
    {
        int cum = 0;
        for (int r = 0; r < 6; r++) {
            ea.src[r] = SRC[r]; ea.dst[r] = DST[r];
            ea.off[r] = offR[r]; ea.csr[r] = csrR[r];
            ea.E[r] = EE[r];
            ea.bs[r] = cum; cum += (EE[r] + 255) / 256;
        }
        ea.bs[6] = cum;
    }
    count_all<<<ea.bs[6], 256>>>(ea);
    {
        ScanArgs sa;
        for (int r = 0; r < 6; r++) { sa.data[r] = offR[r]; sa.n[r] = NDSTA[r]; }
        scan6<<<6, 1024>>>(sa);
    }
    fill_all<<<ea.bs[6], 256>>>(ea);

    // ---- shared gather descriptor (relation pairing per dst type) ----
    // t=0: m <- (rel0 from c, rel4 from d); t=1: d <- (rel1, rel2); t=2: c <- (rel3, rel5)
    const int relA[3] = {0, 1, 3};
    const int relB[3] = {4, 2, 5};
    float* AGGt[3] = {AGGm, AGGd, AGGc};
    const int NT[3] = {NM, ND, NC};
    Gather3 ga;
    {
        int cum = 0;
        for (int t = 0; t < 3; t++) {
            ga.offA[t] = offR[relA[t]]; ga.csrA[t] = csrR[relA[t]];
            ga.offB[t] = offR[relB[t]]; ga.csrB[t] = csrR[relB[t]];
            ga.PA[t] = PR[relA[t]]; ga.PB[t] = PR[relB[t]];
            ga.out[t] = AGGt[t];
            ga.ws[t] = cum; cum += NT[t];
        }
        ga.ws[3] = cum;
    }
    const int gatherBlocks = ((NM + ND + NC) * 32 + 255) / 256;

    // ---- layer 1: projections (1 launch) ----
    Proj6 p1;
    {
        int cum = 0;
        for (int r = 0; r < 6; r++) {
            p1.X[r] = X1[srcType[r]];
            p1.W[r] = W1l + (size_t)r * 8192;
            p1.Y[r] = PR[r];
            p1.M[r] = NSRC[r];
            p1.bs[r] = cum; cum += (NSRC[r] + 255) / 256;
        }
        p1.bs[6] = cum;
    }
    proj_all<4><<<p1.bs[6], 256>>>(p1);

    // ---- layer 1: gathers (1 launch) ----
    gather_all<<<gatherBlocks, 256>>>(ga);

    // ---- layer 1: combines (1 launch) ----
    const float* XD[3] = {xm, xd, xc};
    float* HT[3] = {Hm, Hd, Hc};
    Comb3 c1;
    {
        int cum = 0;
        for (int t = 0; t < 3; t++) {
            c1.X[t]  = XD[t];
            c1.Wa[t] = W1r + (size_t)relA[t] * 8192;
            c1.Wb[t] = W1r + (size_t)relB[t] * 8192;
            c1.ba[t] = b1 + (size_t)relA[t] * 64;
            c1.bb[t] = b1 + (size_t)relB[t] * 64;
            c1.AGG[t] = AGGt[t];
            c1.Y[t] = HT[t];
            c1.M[t] = NT[t];
            c1.bs[t] = cum; cum += (NT[t] + 255) / 256;
        }
        c1.bs[3] = cum;
    }
    combine1_all<<<c1.bs[3], 256>>>(c1);

    // ---- layer 2: projections (1 launch) ----
    Proj6 p2;
    {
        int cum = 0;
        for (int r = 0; r < 6; r++) {
            p2.X[r] = HX[srcType[r]];
            p2.W[r] = W2l + (size_t)r * 4096;
            p2.Y[r] = PR[r];
            p2.M[r] = NSRC[r];
            p2.bs[r] = cum; cum += (NSRC[r] + 255) / 256;
        }
        p2.bs[6] = cum;
    }
    proj_all<2><<<p2.bs[6], 256>>>(p2);

    // ---- layer 2: gathers (1 launch) ----
    gather_all<<<gatherBlocks, 256>>>(ga);

    // ---- final: combine2 + residual + l2norm (1 launch) ----
    const float* HDst[3] = {Hm, Hd, Hc};
    const float* XRes[3] = {xm, xd, xc};
    const int resIdx[3] = {1, 2, 0};  // W_res rows: 0=c,1=m,2=d
    float* OT[3] = {Om, Od, Oc};
    Final3 f;
    {
        int cum = 0;
        for (int t = 0; t < 3; t++) {
            f.Hs[t]  = HDst[t];
            f.W2a[t] = W2r + (size_t)relA[t] * 4096;
            f.W2b[t] = W2r + (size_t)relB[t] * 4096;
            f.b2a[t] = b2 + (size_t)relA[t] * 64;
            f.b2b[t] = b2 + (size_t)relB[t] * 64;
            f.AGG[t] = AGGt[t];
            f.Xr[t]  = XRes[t];
            f.Wr[t]  = Wres + (size_t)resIdx[t] * 8192;
            f.br[t]  = bres + (size_t)resIdx[t] * 64;
            f.Y[t] = OT[t];
            f.M[t] = NT[t];
            f.bs[t] = cum; cum += (NT[t] + 255) / 256;
        }
        f.bs[3] = cum;
    }
    final_all<<<f.bs[3], 256>>>(f);
}